// round 13
// baseline (speedup 1.0000x reference)
#include <cuda_runtime.h>
#include <cuda_fp16.h>
#include <cstdint>

#define N_NODES 50000
#define N_EDGES 1600000
#define D_FEAT  64
#define D_OUT   128
#define K_DIM   192
#define BM      64           // rows per CTA tile

#define LDA    72            // fp16 leading dim of A rows (144 B, ldmatrix conflict-free)
#define CHS    9216          // A chunk stride: 64 rows * 144 B
#define GBUF   36864         // buffer: max(A 3*9216=27648, stage 64*144*4=36864)
#define SMEM_DYN 73728       // two buffers
#define LDST   144           // fp32 stage leading dim (floats)

// Weights pre-packed in mma-fragment PAIR order: [12 ksteps][8 ngroup-pairs][32 lanes] uint4
// uint4 = { b(2p).lo, b(2p).hi, b(2p+1).lo, b(2p+1).hi }
__device__ __align__(16) uint4 g_We_f[12 * 8 * 32];
__device__ __align__(16) uint4 g_Wn_f[12 * 8 * 32];
__device__ float g_received[(size_t)N_NODES * D_OUT];

// ---------------------------------------------------------------------------
static __device__ __forceinline__ uint32_t smem_u32(const void* p) {
    uint32_t a;
    asm("{ .reg .u64 t; cvta.to.shared.u64 t, %1; cvt.u32.u64 %0, t; }" : "=r"(a) : "l"(p));
    return a;
}
static __device__ __forceinline__ void ldm4(uint32_t* r, uint32_t addr) {
    asm volatile("ldmatrix.sync.aligned.m8n8.x4.shared.b16 {%0,%1,%2,%3}, [%4];"
                 : "=r"(r[0]), "=r"(r[1]), "=r"(r[2]), "=r"(r[3]) : "r"(addr));
}
static __device__ __forceinline__ void mma16816(float* c, const uint32_t* a, const uint32_t* b) {
    asm volatile(
        "mma.sync.aligned.m16n8k16.row.col.f32.f16.f16.f32 "
        "{%0,%1,%2,%3}, {%4,%5,%6,%7}, {%8,%9}, {%0,%1,%2,%3};"
        : "+f"(c[0]), "+f"(c[1]), "+f"(c[2]), "+f"(c[3])
        : "r"(a[0]), "r"(a[1]), "r"(a[2]), "r"(a[3]), "r"(b[0]), "r"(b[1]));
}

// ---------------------------------------------------------------------------
// Pack W (fp32 [k][n]) into paired mma B-fragment layout.
// lane l of fragment (ks, g): n = g*8 + l/4, k0 = ks*16 + (l%4)*2
//   b.lo = half2(W[k0][n], W[k0+1][n]);  b.hi = half2(W[k0+8][n], W[k0+9][n])
// ---------------------------------------------------------------------------
__global__ void prep_w_kernel(const float* __restrict__ We, const float* __restrict__ Wn) {
    int idx = blockIdx.x * blockDim.x + threadIdx.x;
    if (idx >= 2 * 12 * 8 * 32) return;
    int m    = idx / (12 * 8 * 32);
    int rest = idx % (12 * 8 * 32);
    int l    = rest & 31;
    int pid  = rest >> 5;
    int s    = pid >> 3;          // kstep
    int p    = pid & 7;           // ngroup pair
    const float* W = m ? Wn : We;
    int k0 = s * 16 + (l & 3) * 2;
    uint4 out;
    #pragma unroll
    for (int h = 0; h < 2; h++) {
        int n = (2 * p + h) * 8 + (l >> 2);
        __half2 b0 = __floats2half2_rn(W[(size_t)k0 * D_OUT + n],       W[(size_t)(k0 + 1) * D_OUT + n]);
        __half2 b1 = __floats2half2_rn(W[(size_t)(k0 + 8) * D_OUT + n], W[(size_t)(k0 + 9) * D_OUT + n]);
        if (h == 0) { out.x = *(uint32_t*)&b0; out.y = *(uint32_t*)&b1; }
        else        { out.z = *(uint32_t*)&b0; out.w = *(uint32_t*)&b1; }
    }
    (m ? g_Wn_f : g_We_f)[rest] = out;
}

__global__ void zero_received_kernel() {
    size_t n4 = (size_t)N_NODES * D_OUT / 4;
    float4* p = reinterpret_cast<float4*>(g_received);
    for (size_t i = blockIdx.x * blockDim.x + threadIdx.x; i < n4;
         i += (size_t)gridDim.x * blockDim.x)
        p[i] = make_float4(0.f, 0.f, 0.f, 0.f);
}

// ---------------------------------------------------------------------------
// Persistent fused GEMM: 128-thread CTA owns a 64-row tile (mt=4 per warp,
// B frags reused over 64 rows); 3 CTAs/SM anti-phase; high reg cap lets
// ptxas pipeline loads. Cross-tile double-buffered gather; fused scatter (EDGE).
// ---------------------------------------------------------------------------
template <bool EDGE>
__global__ __launch_bounds__(128, 3)
void gnn_kernel(const float* __restrict__ nodes,
                const float* __restrict__ edges,
                const int*   __restrict__ senders,
                const int*   __restrict__ receivers,
                const float* __restrict__ bias,
                float* __restrict__ outbuf,
                int t0, int ntiles)
{
    extern __shared__ __align__(16) char sp[];
    const uint32_t smbase = smem_u32(sp);

    const int tid = threadIdx.x;
    const int wid = tid >> 5;             // 0..3
    const int lid = tid & 31;
    const int wn  = wid * 32;             // warp n-origin
    const int pb  = wid * 2;              // B ngroup-pair base

    const int grow  = tid >> 1;           // 0..63 gather row
    const int gcol0 = (tid & 1) * 32;     // gather col base (32 floats each)

    const uint4* __restrict__ Wf = EDGE ? g_We_f : g_Wn_f;

    const int a_row = (lid & 7) + ((lid >> 3) & 1) * 8;
    const int a_kof = (lid >> 4) * 8;

    const int stride = gridDim.x;
    const int tend   = t0 + ntiles;
    int t = t0 + blockIdx.x;

    // gather one chunk of tile tt into buffer `buf` (this thread: 32 floats)
    auto do_gather = [&](int c, int tt, int rs_x, int rr_x, int buf) {
        int m0n = tt * BM;
        const float* src;
        if (EDGE) {
            if (c == 0)      src = edges + (size_t)(m0n + grow) * D_FEAT + gcol0;
            else if (c == 1) src = nodes + (size_t)rs_x * D_FEAT + gcol0;
            else             src = nodes + (size_t)rr_x * D_FEAT + gcol0;
        } else {
            int rg = m0n + grow;
            if (rg >= N_NODES) rg = N_NODES - 1;
            if (c == 0)      src = nodes + (size_t)rg * D_FEAT + gcol0;
            else             src = g_received + (size_t)rg * D_OUT + (c - 1) * 64 + gcol0;
        }
        __half* dst = (__half*)(sp + buf * GBUF + c * CHS) + grow * LDA + gcol0;
        #pragma unroll
        for (int i = 0; i < 8; i++) {
            float4 v = *(const float4*)(src + i * 4);
            __half2 h01 = __floats2half2_rn(v.x, v.y);
            __half2 h23 = __floats2half2_rn(v.z, v.w);
            *(uint2*)(dst + i * 4) = make_uint2(*(uint32_t*)&h01, *(uint32_t*)&h23);
        }
    };

    // ---- prologue: gather first tile into buffer 0 ----
    int rs = 0, rr = 0;
    {
        if (EDGE) {
            rs = senders[t * BM + grow];
            rr = receivers[t * BM + grow];
        }
        #pragma unroll
        for (int c = 0; c < 3; c++) do_gather(c, t, rs, rr, 0);
    }

    int cur = 0;
    for (; t < tend; t += stride) {
        const int tn = t + stride;
        const bool hn = tn < tend;
        int rs_n = 0, rr_n = 0;
        if (EDGE && hn) {
            rs_n = senders[tn * BM + grow];
            rr_n = receivers[tn * BM + grow];
        }
        __syncthreads();                   // A[cur] complete; stage region free

        const uint32_t sA = smbase + cur * GBUF;

        float acc[4][4][4];
        #pragma unroll
        for (int mt = 0; mt < 4; mt++)
            #pragma unroll
            for (int nt = 0; nt < 4; nt++)
                #pragma unroll
                for (int i = 0; i < 4; i++) acc[mt][nt][i] = 0.f;

        #pragma unroll
        for (int c = 0; c < 3; c++) {
            #pragma unroll
            for (int ksl = 0; ksl < 4; ksl++) {
                const int ks = c * 4 + ksl;
                uint32_t ah[4][4];
                uint4 bq[2];
                #pragma unroll
                for (int mt = 0; mt < 4; mt++)
                    ldm4(ah[mt], sA + c * CHS + ((mt * 16 + a_row) * LDA + ksl * 16 + a_kof) * 2);
                bq[0] = __ldg(&Wf[(ks * 8 + pb)     * 32 + lid]);
                bq[1] = __ldg(&Wf[(ks * 8 + pb + 1) * 32 + lid]);
                #pragma unroll
                for (int mt = 0; mt < 4; mt++) {
                    mma16816(acc[mt][0], ah[mt], (const uint32_t*)&bq[0].x);
                    mma16816(acc[mt][1], ah[mt], (const uint32_t*)&bq[0].z);
                    mma16816(acc[mt][2], ah[mt], (const uint32_t*)&bq[1].x);
                    mma16816(acc[mt][3], ah[mt], (const uint32_t*)&bq[1].z);
                }
            }
            // overlap: gather chunk c of next tile into A[cur^1]
            if (hn) do_gather(c, tn, rs_n, rr_n, cur ^ 1);
        }
        __syncthreads();                   // mma reads of A[cur] done

        // ---- epilogue: frags -> stage (cur buffer) -> coalesced out ----
        float* stage = (float*)(sp + cur * GBUF);   // [64][144]
        {
            const int cr = lid >> 2;
            const int cc = (lid & 3) * 2;
            #pragma unroll
            for (int mt = 0; mt < 4; mt++)
                #pragma unroll
                for (int nt = 0; nt < 4; nt++) {
                    int r  = mt * 16 + cr;
                    int cx = wn + nt * 8 + cc;
                    *(float2*)&stage[r * LDST + cx]       = make_float2(acc[mt][nt][0], acc[mt][nt][1]);
                    *(float2*)&stage[(r + 8) * LDST + cx] = make_float2(acc[mt][nt][2], acc[mt][nt][3]);
                }
        }
        __syncthreads();
        {
            const int m0 = t * BM;
            const int gq = tid & 3;
            #pragma unroll
            for (int p = 0; p < 2; p++) {
                const int row = (tid >> 2) + p * 32;       // 0..63
                const bool live = EDGE || (m0 + row) < N_NODES;
                const int rcv = EDGE ? receivers[m0 + row] : 0;
                #pragma unroll
                for (int j = 0; j < 8; j++) {
                    int cx = gq * 4 + j * 16;
                    float4 bb = *(const float4*)&bias[cx];
                    float4 v;
                    v.x = fmaxf(stage[row * LDST + cx + 0] + bb.x, 0.f);
                    v.y = fmaxf(stage[row * LDST + cx + 1] + bb.y, 0.f);
                    v.z = fmaxf(stage[row * LDST + cx + 2] + bb.z, 0.f);
                    v.w = fmaxf(stage[row * LDST + cx + 3] + bb.w, 0.f);
                    if (live) {
                        *(float4*)&outbuf[(size_t)(m0 + row) * D_OUT + cx] = v;
                        if (EDGE) {
                            float* rp = g_received + (size_t)rcv * D_OUT + cx;
                            asm volatile("red.global.add.v4.f32 [%0], {%1,%2,%3,%4};"
                                         :: "l"(rp), "f"(v.x), "f"(v.y), "f"(v.z), "f"(v.w) : "memory");
                        }
                    }
                }
            }
        }
        rs = rs_n; rr = rr_n;
        cur ^= 1;
    }
}

// ---------------------------------------------------------------------------
extern "C" void kernel_launch(void* const* d_in, const int* in_sizes, int n_in,
                              void* d_out, int out_size)
{
    const float* nodes     = (const float*)d_in[0];
    const float* edges     = (const float*)d_in[1];
    const int*   senders   = (const int*)d_in[2];
    const int*   receivers = (const int*)d_in[3];
    const float* W_edge    = (const float*)d_in[4];
    const float* b_edge    = (const float*)d_in[5];
    const float* W_node    = (const float*)d_in[6];
    const float* b_node    = (const float*)d_in[7];

    float* out       = (float*)d_out;
    float* new_nodes = out;
    float* new_edges = out + (size_t)N_NODES * D_OUT;

    cudaFuncSetAttribute(gnn_kernel<true>,  cudaFuncAttributeMaxDynamicSharedMemorySize, SMEM_DYN);
    cudaFuncSetAttribute(gnn_kernel<false>, cudaFuncAttributeMaxDynamicSharedMemorySize, SMEM_DYN);

    const int GRID    = 3 * 148;            // 3 persistent CTAs per SM
    const int E_TILES = N_EDGES / BM;       // 25000
    const int E_HALF  = E_TILES / 2;        // 12500
    const int N_TILES = (N_NODES + BM - 1) / BM;   // 782

    prep_w_kernel<<<(2 * 12 * 8 * 32 + 255) / 256, 256>>>(W_edge, W_node);
    zero_received_kernel<<<592, 256>>>();

    // edge work split across two persistent launches (keeps ncu on an edge launch)
    gnn_kernel<true><<<GRID, 128, SMEM_DYN>>>(
        nodes, edges, senders, receivers, b_edge, new_edges, 0, E_HALF);
    gnn_kernel<true><<<GRID, 128, SMEM_DYN>>>(
        nodes, edges, senders, receivers, b_edge, new_edges, E_HALF, E_TILES - E_HALF);

    gnn_kernel<false><<<GRID, 128, SMEM_DYN>>>(
        nodes, nullptr, nullptr, nullptr, b_node, new_nodes, 0, N_TILES);
}

// round 14
// speedup vs baseline: 1.1484x; 1.1484x over previous
#include <cuda_runtime.h>
#include <cuda_fp16.h>
#include <cstdint>

#define N_NODES 50000
#define N_EDGES 1600000
#define D_FEAT  64
#define D_OUT   128
#define K_DIM   192
#define BM      64

#define LDA    72            // fp16 leading dim of A rows (144 B, ldmatrix conflict-free)
#define CHS    4608          // A chunk stride: 32 rows * 144 B
#define GBUF   13824         // per-group buffer: 3 chunks (A only, no stage)
#define GPART  27648         // per-group partition: 2 buffers
#define SMEM_DYN 55296

// Weights pre-packed in mma-fragment PAIR order: [12 ksteps][8 ngroup-pairs][32 lanes] uint4
// uint4 = { b(2p).lo, b(2p).hi, b(2p+1).lo, b(2p+1).hi }
__device__ __align__(16) uint4 g_We_f[12 * 8 * 32];
__device__ __align__(16) uint4 g_Wn_f[12 * 8 * 32];
__device__ float g_received[(size_t)N_NODES * D_OUT];

// ---------------------------------------------------------------------------
static __device__ __forceinline__ uint32_t smem_u32(const void* p) {
    uint32_t a;
    asm("{ .reg .u64 t; cvta.to.shared.u64 t, %1; cvt.u32.u64 %0, t; }" : "=r"(a) : "l"(p));
    return a;
}
static __device__ __forceinline__ void ldm4(uint32_t* r, uint32_t addr) {
    asm volatile("ldmatrix.sync.aligned.m8n8.x4.shared.b16 {%0,%1,%2,%3}, [%4];"
                 : "=r"(r[0]), "=r"(r[1]), "=r"(r[2]), "=r"(r[3]) : "r"(addr));
}
static __device__ __forceinline__ void mma16816(float* c, const uint32_t* a, const uint32_t* b) {
    asm volatile(
        "mma.sync.aligned.m16n8k16.row.col.f32.f16.f16.f32 "
        "{%0,%1,%2,%3}, {%4,%5,%6,%7}, {%8,%9}, {%0,%1,%2,%3};"
        : "+f"(c[0]), "+f"(c[1]), "+f"(c[2]), "+f"(c[3])
        : "r"(a[0]), "r"(a[1]), "r"(a[2]), "r"(a[3]), "r"(b[0]), "r"(b[1]));
}
// half-CTA barrier: id 1 or 2, 128 threads
static __device__ __forceinline__ void hbar(int wg) {
    asm volatile("bar.sync %0, 128;" :: "r"(wg + 1) : "memory");
}

// ---------------------------------------------------------------------------
// Pack W (fp32 [k][n]) into paired mma B-fragment layout.
// lane l of fragment (ks, g): n = g*8 + l/4, k0 = ks*16 + (l%4)*2
// ---------------------------------------------------------------------------
__global__ void prep_w_kernel(const float* __restrict__ We, const float* __restrict__ Wn) {
    int idx = blockIdx.x * blockDim.x + threadIdx.x;
    if (idx >= 2 * 12 * 8 * 32) return;
    int m    = idx / (12 * 8 * 32);
    int rest = idx % (12 * 8 * 32);
    int l    = rest & 31;
    int pid  = rest >> 5;
    int s    = pid >> 3;          // kstep
    int p    = pid & 7;           // ngroup pair
    const float* W = m ? Wn : We;
    int k0 = s * 16 + (l & 3) * 2;
    uint4 out;
    #pragma unroll
    for (int h = 0; h < 2; h++) {
        int n = (2 * p + h) * 8 + (l >> 2);
        __half2 b0 = __floats2half2_rn(W[(size_t)k0 * D_OUT + n],       W[(size_t)(k0 + 1) * D_OUT + n]);
        __half2 b1 = __floats2half2_rn(W[(size_t)(k0 + 8) * D_OUT + n], W[(size_t)(k0 + 9) * D_OUT + n]);
        if (h == 0) { out.x = *(uint32_t*)&b0; out.y = *(uint32_t*)&b1; }
        else        { out.z = *(uint32_t*)&b0; out.w = *(uint32_t*)&b1; }
    }
    (m ? g_Wn_f : g_We_f)[rest] = out;
}

__global__ void zero_received_kernel() {
    size_t n4 = (size_t)N_NODES * D_OUT / 4;
    float4* p = reinterpret_cast<float4*>(g_received);
    for (size_t i = blockIdx.x * blockDim.x + threadIdx.x; i < n4;
         i += (size_t)gridDim.x * blockDim.x)
        p[i] = make_float4(0.f, 0.f, 0.f, 0.f);
}

// ---------------------------------------------------------------------------
// Persistent fused GEMM: BM=64 tiles; two independent 128-thread pipelines
// with byte-disjoint smem partitions. B frags from L1-resident global;
// cross-tile double-buffered gather; DIRECT fragment epilogue (no stage):
// bias+relu in frags, STG.64 + red.v2 scatter. 2 barriers/tile.
// ---------------------------------------------------------------------------
template <bool EDGE>
__global__ __launch_bounds__(256, 3)
void gnn_kernel(const float* __restrict__ nodes,
                const float* __restrict__ edges,
                const int*   __restrict__ senders,
                const int*   __restrict__ receivers,
                const float* __restrict__ bias,
                float* __restrict__ outbuf,
                int t0, int ntiles)
{
    extern __shared__ __align__(16) char sp[];
    const uint32_t smbase = smem_u32(sp);

    const int tid = threadIdx.x;
    const int wid = tid >> 5;
    const int lid = tid & 31;
    const int wg  = wid >> 2;             // half-CTA group (0 or 1)
    const int wn  = (wid & 3) * 32;       // warp n-origin within group
    const int pb  = (wid & 3) * 2;        // B ngroup-pair base

    const int grow   = tid >> 2;          // 0..63 global tile row (gather)
    const int rlocal = grow & 31;
    const int gq     = tid & 3;
    const int gcol0  = gq * 16;

    const uint4* __restrict__ Wf = EDGE ? g_We_f : g_Wn_f;

    const int a_row = (lid & 7) + ((lid >> 3) & 1) * 8;
    const int a_kof = (lid >> 4) * 8;
    const int cr    = lid >> 2;           // fragment row within 8-row block
    const int cc    = (lid & 3) * 2;      // fragment col pair within 8

    // bias hoisted into registers: 2 cols per nt for this lane
    float2 bb[4];
    #pragma unroll
    for (int nt = 0; nt < 4; nt++)
        bb[nt] = *(const float2*)&bias[wn + nt * 8 + cc];

    const uint32_t part = smbase + wg * GPART;

    const int stride = gridDim.x;
    const int tend   = t0 + ntiles;
    int t = t0 + blockIdx.x;

    // gather one chunk of tile tt into this group's buffer `buf`
    auto do_gather = [&](int c, int tt, int rs_x, int rr_x, int buf) {
        int m0n = tt * BM;
        const float* src;
        if (EDGE) {
            if (c == 0)      src = edges + (size_t)(m0n + grow) * D_FEAT + gcol0;
            else if (c == 1) src = nodes + (size_t)rs_x * D_FEAT + gcol0;
            else             src = nodes + (size_t)rr_x * D_FEAT + gcol0;
        } else {
            int rg = m0n + grow;
            if (rg >= N_NODES) rg = N_NODES - 1;
            if (c == 0)      src = nodes + (size_t)rg * D_FEAT + gcol0;
            else             src = g_received + (size_t)rg * D_OUT + (c - 1) * 64 + gcol0;
        }
        __half* dst = (__half*)(sp + wg * GPART + buf * GBUF + c * CHS) + rlocal * LDA + gcol0;
        #pragma unroll
        for (int i = 0; i < 4; i++) {
            float4 v = *(const float4*)(src + i * 4);
            __half2 h01 = __floats2half2_rn(v.x, v.y);
            __half2 h23 = __floats2half2_rn(v.z, v.w);
            *(uint2*)(dst + i * 4) = make_uint2(*(uint32_t*)&h01, *(uint32_t*)&h23);
        }
    };

    // ---- prologue: gather first tile into buffer 0 ----
    int rs = 0, rr = 0;
    {
        if (EDGE) {
            rs = senders[t * BM + grow];
            rr = receivers[t * BM + grow];
        }
        #pragma unroll
        for (int c = 0; c < 3; c++) do_gather(c, t, rs, rr, 0);
    }

    int cur = 0;
    for (; t < tend; t += stride) {
        const int tn = t + stride;
        const bool hn = tn < tend;
        int rs_n = 0, rr_n = 0;
        if (EDGE && hn) {
            rs_n = senders[tn * BM + grow];
            rr_n = receivers[tn * BM + grow];
        }
        hbar(wg);                          // group's A[cur] gather complete

        const uint32_t sA = part + cur * GBUF;

        float acc[2][4][4];
        #pragma unroll
        for (int mt = 0; mt < 2; mt++)
            #pragma unroll
            for (int nt = 0; nt < 4; nt++)
                #pragma unroll
                for (int i = 0; i < 4; i++) acc[mt][nt][i] = 0.f;

        #pragma unroll
        for (int c = 0; c < 3; c++) {
            #pragma unroll
            for (int ksl = 0; ksl < 4; ksl++) {
                const int ks = c * 4 + ksl;
                uint32_t ah[2][4];
                uint4 bq[2];
                ldm4(ah[0], sA + c * CHS + ((     a_row) * LDA + ksl * 16 + a_kof) * 2);
                ldm4(ah[1], sA + c * CHS + ((16 + a_row) * LDA + ksl * 16 + a_kof) * 2);
                bq[0] = __ldg(&Wf[(ks * 8 + pb)     * 32 + lid]);
                bq[1] = __ldg(&Wf[(ks * 8 + pb + 1) * 32 + lid]);
                #pragma unroll
                for (int mt = 0; mt < 2; mt++) {
                    mma16816(acc[mt][0], ah[mt], (const uint32_t*)&bq[0].x);
                    mma16816(acc[mt][1], ah[mt], (const uint32_t*)&bq[0].z);
                    mma16816(acc[mt][2], ah[mt], (const uint32_t*)&bq[1].x);
                    mma16816(acc[mt][3], ah[mt], (const uint32_t*)&bq[1].z);
                }
            }
            // overlap: gather chunk c of next tile into this group's A[cur^1]
            if (hn) do_gather(c, tn, rs_n, rr_n, cur ^ 1);
        }
        hbar(wg);                          // mma reads of A[cur] done (safe for
                                           // next iteration's overwrite)

        // ---- direct fragment epilogue: bias+relu, STG.64, red.v2 scatter ----
        {
            const int m0g = t * BM + wg * 32;
            #pragma unroll
            for (int mt = 0; mt < 2; mt++) {
                #pragma unroll
                for (int half = 0; half < 2; half++) {
                    const int row = m0g + mt * 16 + cr + half * 8;
                    const bool live = EDGE || row < N_NODES;
                    const int rcv = (EDGE && live) ? receivers[row] : 0;
                    #pragma unroll
                    for (int nt = 0; nt < 4; nt++) {
                        float2 v;
                        v.x = fmaxf(acc[mt][nt][half * 2 + 0] + bb[nt].x, 0.f);
                        v.y = fmaxf(acc[mt][nt][half * 2 + 1] + bb[nt].y, 0.f);
                        if (live) {
                            const int col = wn + nt * 8 + cc;
                            *(float2*)&outbuf[(size_t)row * D_OUT + col] = v;
                            if (EDGE) {
                                float* rp = g_received + (size_t)rcv * D_OUT + col;
                                asm volatile("red.global.add.v2.f32 [%0], {%1,%2};"
                                             :: "l"(rp), "f"(v.x), "f"(v.y) : "memory");
                            }
                        }
                    }
                }
            }
        }
        rs = rs_n; rr = rr_n;
        cur ^= 1;
    }
}

// ---------------------------------------------------------------------------
extern "C" void kernel_launch(void* const* d_in, const int* in_sizes, int n_in,
                              void* d_out, int out_size)
{
    const float* nodes     = (const float*)d_in[0];
    const float* edges     = (const float*)d_in[1];
    const int*   senders   = (const int*)d_in[2];
    const int*   receivers = (const int*)d_in[3];
    const float* W_edge    = (const float*)d_in[4];
    const float* b_edge    = (const float*)d_in[5];
    const float* W_node    = (const float*)d_in[6];
    const float* b_node    = (const float*)d_in[7];

    float* out       = (float*)d_out;
    float* new_nodes = out;
    float* new_edges = out + (size_t)N_NODES * D_OUT;

    cudaFuncSetAttribute(gnn_kernel<true>,  cudaFuncAttributeMaxDynamicSharedMemorySize, SMEM_DYN);
    cudaFuncSetAttribute(gnn_kernel<false>, cudaFuncAttributeMaxDynamicSharedMemorySize, SMEM_DYN);

    const int GRID    = 3 * 148;            // 3 persistent CTAs per SM
    const int E_TILES = N_EDGES / BM;       // 25000
    const int E_HALF  = E_TILES / 2;        // 12500
    const int N_TILES = (N_NODES + BM - 1) / BM;   // 782

    prep_w_kernel<<<(2 * 12 * 8 * 32 + 255) / 256, 256>>>(W_edge, W_node);
    zero_received_kernel<<<592, 256>>>();

    // edge work split across two persistent launches (keeps ncu on an edge launch)
    gnn_kernel<true><<<GRID, 256, SMEM_DYN>>>(
        nodes, edges, senders, receivers, b_edge, new_edges, 0, E_HALF);
    gnn_kernel<true><<<GRID, 256, SMEM_DYN>>>(
        nodes, edges, senders, receivers, b_edge, new_edges, E_HALF, E_TILES - E_HALF);

    gnn_kernel<false><<<GRID, 256, SMEM_DYN>>>(
        nodes, nullptr, nullptr, nullptr, b_node, new_nodes, 0, N_TILES);
}